// round 14
// baseline (speedup 1.0000x reference)
#include <cuda_runtime.h>
#include <math_constants.h>

#define BATCH  8
#define NPTS   4096
#define TPB    64               // two warps per block
#define QPT    4                // queries per thread
#define QPB    (TPB * QPT)      // 256 queries per block
#define QTILES (NPTS / QPB)     // 16 query tiles per (dir,b)
#define SPLITS 8                // DB split factor
#define SLICE  (NPTS / SPLITS)  // 512 DB points per block (8KB smem)
#define NQTOT  (2 * BATCH * NPTS)    // 65536 total queries (both dirs)
#define TOTTILES (2 * BATCH * QTILES) // 256 query tiles total

// partial min of expanded val, per DB-slice: [split][flat_query]
__device__ float g_pmin[SPLITS][NQTOT];
// per-tile distance sums (deterministic, written by per-tile last arriver)
__device__ float g_tsum[TOTTILES];
// per-tile completion counters + global tile counter (all self-resetting)
__device__ int   g_tilecnt[TOTTILES];
__device__ int   g_count;

// ---- f32x2 helpers -------------------------------------------------------
__device__ __forceinline__ unsigned long long pk(float lo, float hi) {
    unsigned long long r;
    asm("mov.b64 %0, {%1, %2};" : "=l"(r) : "f"(lo), "f"(hi));
    return r;
}
__device__ __forceinline__ unsigned long long fma2(unsigned long long a,
                                                   unsigned long long b,
                                                   unsigned long long c) {
    unsigned long long r;
    asm("fma.rn.f32x2 %0, %1, %2, %3;" : "=l"(r) : "l"(a), "l"(b), "l"(c));
    return r;
}
__device__ __forceinline__ void unpk(unsigned long long v, float& lo, float& hi) {
    asm("mov.b64 {%0, %1}, %2;" : "=f"(lo), "=f"(hi) : "l"(v));
}

// One block = 256 queries x 512-point DB slice, plus fused combine/finalize tails.
// grid = (QTILES*SPLITS, BATCH, 2). dir 0: queries=tar, DB=src ; dir 1: swapped.
__global__ __launch_bounds__(TPB, 13)
void chamfer_kernel(const float* __restrict__ tar, const float* __restrict__ src,
                    float* __restrict__ out) {
    const int dir   = blockIdx.z;
    const float* qraw = (dir == 0) ? tar : src;
    const float* draw = (dir == 0) ? src : tar;

    const int b     = blockIdx.y;
    const int tile  = blockIdx.x / SPLITS;
    const int split = blockIdx.x % SPLITS;
    const int tid   = threadIdx.x;

    // 4 queries per thread, block-stride
    unsigned long long qx2[QPT], qy2[QPT], qz2[QPT];
    #pragma unroll
    for (int k = 0; k < QPT; k++) {
        const int qi = tile * QPB + k * TPB + tid;
        const float* qp = qraw + (size_t)(b * NPTS + qi) * 3;
        float x = qp[0], y = qp[1], z = qp[2];
        qx2[k] = pk(x, x); qy2[k] = pk(y, y); qz2[k] = pk(z, z);
    }

    const float* dbb = draw + (size_t)(b * NPTS + split * SLICE) * 3;

    // pair-SoA smem: sA[j] = {pack(-2x0,-2x1), pack(-2y0,-2y1)}
    //                sB[j] = {pack(-2z0,-2z1), pack(|p0|^2,|p1|^2)}
    __shared__ ulonglong2 sA[SLICE / 2];
    __shared__ ulonglong2 sB[SLICE / 2];

    #pragma unroll 2
    for (int j = tid; j < SLICE / 2; j += TPB) {
        const float2* p2 = (const float2*)(dbb + (size_t)(2 * j) * 3);
        float2 v0 = p2[0], v1 = p2[1], v2 = p2[2];
        // point0 = (v0.x, v0.y, v1.x), point1 = (v1.y, v2.x, v2.y)
        float n0 = fmaf(v0.x, v0.x, fmaf(v0.y, v0.y, v1.x * v1.x));
        float n1 = fmaf(v1.y, v1.y, fmaf(v2.x, v2.x, v2.y * v2.y));
        sA[j] = make_ulonglong2(pk(-2.f * v0.x, -2.f * v1.y),
                                pk(-2.f * v0.y, -2.f * v2.x));
        sB[j] = make_ulonglong2(pk(-2.f * v1.x, -2.f * v2.y),
                                pk(n0, n1));
    }
    __syncthreads();

    float mlo[QPT], mhi[QPT];
    #pragma unroll
    for (int k = 0; k < QPT; k++) { mlo[k] = mhi[k] = CUDART_INF_F; }

    #pragma unroll 4
    for (int j = 0; j < SLICE / 2; j++) {
        ulonglong2 pa = sA[j];
        ulonglong2 pb = sB[j];

        #pragma unroll
        for (int k = 0; k < QPT; k++) {
            unsigned long long t = fma2(qz2[k], pb.x, pb.y);
            t = fma2(qy2[k], pa.y, t);
            t = fma2(qx2[k], pa.x, t);
            float lo, hi; unpk(t, lo, hi);
            mlo[k] = fminf(mlo[k], lo);
            mhi[k] = fminf(mhi[k], hi);
        }
    }

    // write per-(query, slice) partial min-val (coalesced per k)
    const int tileid = (dir * BATCH + b) * QTILES + tile;   // 0..255
    const int base   = (dir * BATCH + b) * NPTS + tile * QPB;
    #pragma unroll
    for (int k = 0; k < QPT; k++)
        g_pmin[split][base + k * TPB + tid] = fminf(mlo[k], mhi[k]);

    // ---- fused combine: per-tile last arriver folds the 8 splits ----------
    __shared__ int s_last;
    __threadfence();
    __syncthreads();
    if (tid == 0)
        s_last = (atomicAdd(&g_tilecnt[tileid], 1) == SPLITS - 1);
    __syncthreads();
    if (!s_last) return;

    __threadfence();  // acquire: other splits' g_pmin writes
    float acc = 0.f;
    #pragma unroll
    for (int k = 0; k < QPT; k++) {
        const int fq = base + k * TPB + tid;
        float m = g_pmin[0][fq];
        #pragma unroll
        for (int s = 1; s < SPLITS; s++) m = fminf(m, g_pmin[s][fq]);
        // recover query coords from packed regs (lo half = coord)
        float x, y, z, dummy;
        unpk(qx2[k], x, dummy); unpk(qy2[k], y, dummy); unpk(qz2[k], z, dummy);
        const float qn = fmaf(x, x, fmaf(y, y, z * z));
        acc += sqrtf(fmaxf(qn + m, 0.f));
    }

    // deterministic block-sum (2 warps)
    #pragma unroll
    for (int o = 16; o > 0; o >>= 1)
        acc += __shfl_down_sync(0xffffffffu, acc, o);
    __shared__ float wsum[2];
    __shared__ int s_glast;
    if ((tid & 31) == 0) wsum[tid >> 5] = acc;
    __syncthreads();
    if (tid == 0) {
        g_tsum[tileid]    = wsum[0] + wsum[1];
        g_tilecnt[tileid] = 0;                 // reset for next graph replay
        __threadfence();
        s_glast = (atomicAdd(&g_count, 1) == TOTTILES - 1);
    }
    __syncthreads();
    if (!s_glast) return;

    // ---- fused finalize: globally last tile reduces 256 tile sums ---------
    __threadfence();  // acquire: all g_tsum writes
    // dir0 tiles: [0,128), dir1 tiles: [128,256); fixed summation order
    float v0 = g_tsum[tid]       + g_tsum[tid + 64];
    float v1 = g_tsum[128 + tid] + g_tsum[192 + tid];
    #pragma unroll
    for (int o = 16; o > 0; o >>= 1) {
        v0 += __shfl_down_sync(0xffffffffu, v0, o);
        v1 += __shfl_down_sync(0xffffffffu, v1, o);
    }
    __shared__ float w0[2], w1[2];
    if ((tid & 31) == 0) { w0[tid >> 5] = v0; w1[tid >> 5] = v1; }
    __syncthreads();
    if (tid == 0) {
        const float inv = 1.f / (float)(BATCH * NPTS);
        float complete = (w0[0] + w0[1]) * inv;   // dir 0 (tar -> src)
        float accuracy = (w1[0] + w1[1]) * inv;   // dir 1 (src -> tar)
        out[0] = accuracy;
        out[1] = complete;
        out[2] = 0.5f * (accuracy + complete);
        g_count = 0;                               // reset for next replay
    }
}

extern "C" void kernel_launch(void* const* d_in, const int* in_sizes, int n_in,
                              void* d_out, int out_size) {
    const float* tar = (const float*)d_in[0];
    const float* src = (const float*)d_in[1];
    float* out = (float*)d_out;

    chamfer_kernel<<<dim3(QTILES * SPLITS, BATCH, 2), TPB>>>(tar, src, out);
}

// round 16
// speedup vs baseline: 1.0410x; 1.0410x over previous
#include <cuda_runtime.h>
#include <math_constants.h>

#define BATCH  8
#define NPTS   4096
#define TPB    64               // two warps per block
#define QPT    4                // queries per thread
#define QPB    (TPB * QPT)      // 256 queries per block
#define QTILES (NPTS / QPB)     // 16 query tiles per (dir,b)
#define SPLITS 8                // DB split factor
#define SLICE  (NPTS / SPLITS)  // 512 DB points per block (8KB smem)
#define NQTOT  (2 * BATCH * NPTS)   // 65536 total queries (both dirs)

// partial min of expanded val, per DB-slice: [split][flat_query]
__device__ float g_pmin[SPLITS][NQTOT];
// per-block partial sums from combine kernel + completion counter
#define CGRID 512
__device__ float g_bpart[CGRID];
__device__ int   g_count;   // zero-init; last combine block resets to 0

// ---- f32x2 helpers -------------------------------------------------------
__device__ __forceinline__ unsigned long long pk(float lo, float hi) {
    unsigned long long r;
    asm("mov.b64 %0, {%1, %2};" : "=l"(r) : "f"(lo), "f"(hi));
    return r;
}
__device__ __forceinline__ unsigned long long fma2(unsigned long long a,
                                                   unsigned long long b,
                                                   unsigned long long c) {
    unsigned long long r;
    asm("fma.rn.f32x2 %0, %1, %2, %3;" : "=l"(r) : "l"(a), "l"(b), "l"(c));
    return r;
}
__device__ __forceinline__ void unpk(unsigned long long v, float& lo, float& hi) {
    asm("mov.b64 {%0, %1}, %2;" : "=f"(lo), "=f"(hi) : "l"(v));
}

// One block = 256 queries x 512-point DB slice.
// grid = (QTILES*SPLITS, BATCH, 2). dir 0: queries=tar, DB=src ; dir 1: swapped.
__global__ __launch_bounds__(TPB, 13)
void chamfer_kernel(const float* __restrict__ tar, const float* __restrict__ src) {
    const int dir   = blockIdx.z;
    const float* qraw = (dir == 0) ? tar : src;
    const float* draw = (dir == 0) ? src : tar;

    const int b     = blockIdx.y;
    const int tile  = blockIdx.x / SPLITS;
    const int split = blockIdx.x % SPLITS;
    const int tid   = threadIdx.x;

    // 4 queries per thread, block-stride
    unsigned long long qx2[QPT], qy2[QPT], qz2[QPT];
    #pragma unroll
    for (int k = 0; k < QPT; k++) {
        const int qi = tile * QPB + k * TPB + tid;
        const float* qp = qraw + (size_t)(b * NPTS + qi) * 3;
        float x = qp[0], y = qp[1], z = qp[2];
        qx2[k] = pk(x, x); qy2[k] = pk(y, y); qz2[k] = pk(z, z);
    }

    const float* dbb = draw + (size_t)(b * NPTS + split * SLICE) * 3;

    // pair-SoA smem: sA[j] = {pack(-2x0,-2x1), pack(-2y0,-2y1)}
    //                sB[j] = {pack(-2z0,-2z1), pack(|p0|^2,|p1|^2)}
    __shared__ ulonglong2 sA[SLICE / 2];
    __shared__ ulonglong2 sB[SLICE / 2];

    // fill + pack (whole slice fits; 2 warps cooperate)
    #pragma unroll 2
    for (int j = tid; j < SLICE / 2; j += TPB) {
        const float2* p2 = (const float2*)(dbb + (size_t)(2 * j) * 3);
        float2 v0 = p2[0], v1 = p2[1], v2 = p2[2];
        // point0 = (v0.x, v0.y, v1.x), point1 = (v1.y, v2.x, v2.y)
        float n0 = fmaf(v0.x, v0.x, fmaf(v0.y, v0.y, v1.x * v1.x));
        float n1 = fmaf(v1.y, v1.y, fmaf(v2.x, v2.x, v2.y * v2.y));
        sA[j] = make_ulonglong2(pk(-2.f * v0.x, -2.f * v1.y),
                                pk(-2.f * v0.y, -2.f * v2.x));
        sB[j] = make_ulonglong2(pk(-2.f * v1.x, -2.f * v2.y),
                                pk(n0, n1));
    }
    __syncthreads();

    // 8 accumulators: lo/hi halves per query (merged across j)
    float mlo[QPT], mhi[QPT];
    #pragma unroll
    for (int k = 0; k < QPT; k++) { mlo[k] = mhi[k] = CUDART_INF_F; }

    #pragma unroll 4
    for (int j = 0; j < SLICE / 2; j++) {
        ulonglong2 pa = sA[j];
        ulonglong2 pb = sB[j];

        #pragma unroll
        for (int k = 0; k < QPT; k++) {
            unsigned long long t = fma2(qz2[k], pb.x, pb.y);
            t = fma2(qy2[k], pa.y, t);
            t = fma2(qx2[k], pa.x, t);
            float lo, hi; unpk(t, lo, hi);
            mlo[k] = fminf(mlo[k], lo);
            mhi[k] = fminf(mhi[k], hi);
        }
    }

    // write per-(query, slice) partial min-val (coalesced per k)
    const int base = (dir * BATCH + b) * NPTS + tile * QPB;
    #pragma unroll
    for (int k = 0; k < QPT; k++)
        g_pmin[split][base + k * TPB + tid] = fminf(mlo[k], mhi[k]);

    // allow PDL secondary (combine) to begin launching
    cudaTriggerProgrammaticLaunchCompletion();
}

// Combine slices, add |q|^2, sqrt, sum; last block folds g_bpart -> out.
// Launched with PDL: pre-sync part (query load + |q|^2) overlaps chamfer.
// grid=(CGRID=512), 128 threads, 1 query/thread.
__global__ void combine_kernel(const float* __restrict__ tar, const float* __restrict__ src,
                               float* __restrict__ out) {
    const int t  = threadIdx.x;
    const int fq = blockIdx.x * 128 + t;      // flat query id
    const int dir = fq >> 15;                  // 32768 queries per dir
    const int rem = fq & 32767;                // b*NPTS + qi
    const float* qraw = (dir == 0) ? tar : src;
    const float* qp = qraw + (size_t)rem * 3;
    const float x = qp[0], y = qp[1], z = qp[2];
    const float qn = fmaf(x, x, fmaf(y, y, z * z));

    // gate g_pmin reads on full completion (and memory visibility) of chamfer
    cudaGridDependencySynchronize();

    float m = g_pmin[0][fq];
    #pragma unroll
    for (int s = 1; s < SPLITS; s++) m = fminf(m, g_pmin[s][fq]);
    float acc = sqrtf(fmaxf(qn + m, 0.f));

    #pragma unroll
    for (int o = 16; o > 0; o >>= 1)
        acc += __shfl_down_sync(0xffffffffu, acc, o);

    __shared__ float ws[4];
    __shared__ int is_last;
    if ((t & 31) == 0) ws[t >> 5] = acc;
    __syncthreads();
    if (t == 0) {
        float sblk = ws[0] + ws[1] + ws[2] + ws[3];
        g_bpart[blockIdx.x] = sblk;   // blocks [0,256) = dir0, [256,512) = dir1
        __threadfence();
        is_last = (atomicAdd(&g_count, 1) == CGRID - 1);
    }
    __syncthreads();

    if (is_last) {
        __threadfence();  // acquire: make all g_bpart writes visible
        // 128 threads x 4 partials each; keep dir halves separate
        float v0 = 0.f, v1 = 0.f;
        #pragma unroll
        for (int i = 0; i < 2; i++) {
            v0 += g_bpart[i * 128 + t];          // [0,256)  = dir0
            v1 += g_bpart[256 + i * 128 + t];    // [256,512)= dir1
        }
        #pragma unroll
        for (int o = 16; o > 0; o >>= 1) {
            v0 += __shfl_down_sync(0xffffffffu, v0, o);
            v1 += __shfl_down_sync(0xffffffffu, v1, o);
        }
        __shared__ float w0[4], w1[4];
        if ((t & 31) == 0) { w0[t >> 5] = v0; w1[t >> 5] = v1; }
        __syncthreads();
        if (t == 0) {
            const float inv = 1.f / (float)(BATCH * NPTS);
            float complete = (w0[0] + w0[1] + w0[2] + w0[3]) * inv;  // dir 0
            float accuracy = (w1[0] + w1[1] + w1[2] + w1[3]) * inv;  // dir 1
            out[0] = accuracy;
            out[1] = complete;
            out[2] = 0.5f * (accuracy + complete);
            g_count = 0;   // reset for next graph replay (deterministic)
        }
    }
}

extern "C" void kernel_launch(void* const* d_in, const int* in_sizes, int n_in,
                              void* d_out, int out_size) {
    const float* tar = (const float*)d_in[0];
    const float* src = (const float*)d_in[1];
    float* out = (float*)d_out;

    chamfer_kernel<<<dim3(QTILES * SPLITS, BATCH, 2), TPB>>>(tar, src);

    // PDL launch: combine starts launching while chamfer drains; its g_pmin
    // reads are gated by cudaGridDependencySynchronize() in-kernel.
    cudaLaunchConfig_t cfg = {};
    cfg.gridDim  = dim3(CGRID, 1, 1);
    cfg.blockDim = dim3(128, 1, 1);
    cfg.dynamicSmemBytes = 0;
    cfg.stream = 0;
    cudaLaunchAttribute attr[1];
    attr[0].id = cudaLaunchAttributeProgrammaticStreamSerialization;
    attr[0].val.programmaticStreamSerializationAllowed = 1;
    cfg.attrs = attr;
    cfg.numAttrs = 1;
    cudaLaunchKernelEx(&cfg, combine_kernel, tar, src, out);
}

// round 17
// speedup vs baseline: 1.0463x; 1.0051x over previous
#include <cuda_runtime.h>
#include <math_constants.h>

#define BATCH  8
#define NPTS   4096
#define TPB    64               // two warps per block
#define QPT    4                // queries per thread
#define QPB    (TPB * QPT)      // 256 queries per block
#define QTILES (NPTS / QPB)     // 16 query tiles per (dir,b)
#define SPLITS 8                // DB split factor
#define SLICE  (NPTS / SPLITS)  // 512 DB points per block (8KB smem)
#define NQTOT  (2 * BATCH * NPTS)   // 65536 total queries (both dirs)

// order-reversed-encoded min over splits: max(enc) == min(float).
// zero-initialized at module load == "+infinity"; combine resets to 0 per run.
__device__ unsigned int g_minenc[NQTOT];
// per-block partial sums from combine kernel + completion counter
#define CGRID 512
__device__ float g_bpart[CGRID];
__device__ int   g_count;   // zero-init; last combine block resets to 0

// ---- order-reversed float<->uint encoding --------------------------------
// enc strictly DECREASING in f; all valid enc > 0, so 0 acts as +inf.
__device__ __forceinline__ unsigned int enc_desc(float f) {
    unsigned int b = __float_as_uint(f);
    return (f >= 0.f) ? ~(b | 0x80000000u) : b;
}
__device__ __forceinline__ float dec_desc(unsigned int u) {
    return (u & 0x80000000u) ? __uint_as_float(u)
                             : __uint_as_float(~u & 0x7FFFFFFFu);
}

// ---- f32x2 helpers -------------------------------------------------------
__device__ __forceinline__ unsigned long long pk(float lo, float hi) {
    unsigned long long r;
    asm("mov.b64 %0, {%1, %2};" : "=l"(r) : "f"(lo), "f"(hi));
    return r;
}
__device__ __forceinline__ unsigned long long fma2(unsigned long long a,
                                                   unsigned long long b,
                                                   unsigned long long c) {
    unsigned long long r;
    asm("fma.rn.f32x2 %0, %1, %2, %3;" : "=l"(r) : "l"(a), "l"(b), "l"(c));
    return r;
}
__device__ __forceinline__ void unpk(unsigned long long v, float& lo, float& hi) {
    asm("mov.b64 {%0, %1}, %2;" : "=f"(lo), "=f"(hi) : "l"(v));
}

// One block = 256 queries x 512-point DB slice.
// grid = (QTILES*SPLITS, BATCH, 2). dir 0: queries=tar, DB=src ; dir 1: swapped.
// launch_bounds(64, 14): regs<=72 (was 66) -> 14 blocks/SM -> single wave.
__global__ __launch_bounds__(TPB, 14)
void chamfer_kernel(const float* __restrict__ tar, const float* __restrict__ src) {
    const int dir   = blockIdx.z;
    const float* qraw = (dir == 0) ? tar : src;
    const float* draw = (dir == 0) ? src : tar;

    const int b     = blockIdx.y;
    const int tile  = blockIdx.x / SPLITS;
    const int split = blockIdx.x % SPLITS;
    const int tid   = threadIdx.x;

    // 4 queries per thread, block-stride
    unsigned long long qx2[QPT], qy2[QPT], qz2[QPT];
    #pragma unroll
    for (int k = 0; k < QPT; k++) {
        const int qi = tile * QPB + k * TPB + tid;
        const float* qp = qraw + (size_t)(b * NPTS + qi) * 3;
        float x = qp[0], y = qp[1], z = qp[2];
        qx2[k] = pk(x, x); qy2[k] = pk(y, y); qz2[k] = pk(z, z);
    }

    const float* dbb = draw + (size_t)(b * NPTS + split * SLICE) * 3;

    // pair-SoA smem: sA[j] = {pack(-2x0,-2x1), pack(-2y0,-2y1)}
    //                sB[j] = {pack(-2z0,-2z1), pack(|p0|^2,|p1|^2)}
    __shared__ ulonglong2 sA[SLICE / 2];
    __shared__ ulonglong2 sB[SLICE / 2];

    // fill + pack (whole slice fits; 2 warps cooperate)
    #pragma unroll 2
    for (int j = tid; j < SLICE / 2; j += TPB) {
        const float2* p2 = (const float2*)(dbb + (size_t)(2 * j) * 3);
        float2 v0 = p2[0], v1 = p2[1], v2 = p2[2];
        // point0 = (v0.x, v0.y, v1.x), point1 = (v1.y, v2.x, v2.y)
        float n0 = fmaf(v0.x, v0.x, fmaf(v0.y, v0.y, v1.x * v1.x));
        float n1 = fmaf(v1.y, v1.y, fmaf(v2.x, v2.x, v2.y * v2.y));
        sA[j] = make_ulonglong2(pk(-2.f * v0.x, -2.f * v1.y),
                                pk(-2.f * v0.y, -2.f * v2.x));
        sB[j] = make_ulonglong2(pk(-2.f * v1.x, -2.f * v2.y),
                                pk(n0, n1));
    }
    __syncthreads();

    // 8 accumulators: lo/hi halves per query (merged across j)
    float mlo[QPT], mhi[QPT];
    #pragma unroll
    for (int k = 0; k < QPT; k++) { mlo[k] = mhi[k] = CUDART_INF_F; }

    #pragma unroll 4
    for (int j = 0; j < SLICE / 2; j++) {
        ulonglong2 pa = sA[j];
        ulonglong2 pb = sB[j];

        #pragma unroll
        for (int k = 0; k < QPT; k++) {
            unsigned long long t = fma2(qz2[k], pb.x, pb.y);
            t = fma2(qy2[k], pa.y, t);
            t = fma2(qx2[k], pa.x, t);
            float lo, hi; unpk(t, lo, hi);
            mlo[k] = fminf(mlo[k], lo);
            mhi[k] = fminf(mhi[k], hi);
        }
    }

    // fold split-min via encoded atomic max (exact, order-independent)
    const int base = (dir * BATCH + b) * NPTS + tile * QPB;
    #pragma unroll
    for (int k = 0; k < QPT; k++) {
        float mn = fminf(mlo[k], mhi[k]);
        atomicMax(&g_minenc[base + k * TPB + tid], enc_desc(mn));
    }
}

// Decode per-query min, add |q|^2, sqrt, sum; reset g_minenc for next replay;
// last block folds g_bpart -> out. grid=(CGRID=512), 128 threads, 1 query/thread.
__global__ void combine_kernel(const float* __restrict__ tar, const float* __restrict__ src,
                               float* __restrict__ out) {
    const int t  = threadIdx.x;
    const int fq = blockIdx.x * 128 + t;      // flat query id
    const int dir = fq >> 15;                  // 32768 queries per dir
    const int rem = fq & 32767;                // b*NPTS + qi
    const float* qraw = (dir == 0) ? tar : src;
    const float* qp = qraw + (size_t)rem * 3;
    const float x = qp[0], y = qp[1], z = qp[2];
    const float qn = fmaf(x, x, fmaf(y, y, z * z));

    float m = dec_desc(g_minenc[fq]);
    g_minenc[fq] = 0u;                         // reset (= +inf) for next replay
    float acc = sqrtf(fmaxf(qn + m, 0.f));

    #pragma unroll
    for (int o = 16; o > 0; o >>= 1)
        acc += __shfl_down_sync(0xffffffffu, acc, o);

    __shared__ float ws[4];
    __shared__ int is_last;
    if ((t & 31) == 0) ws[t >> 5] = acc;
    __syncthreads();
    if (t == 0) {
        float sblk = ws[0] + ws[1] + ws[2] + ws[3];
        g_bpart[blockIdx.x] = sblk;   // blocks [0,256) = dir0, [256,512) = dir1
        __threadfence();
        is_last = (atomicAdd(&g_count, 1) == CGRID - 1);
    }
    __syncthreads();

    if (is_last) {
        __threadfence();  // acquire: make all g_bpart writes visible
        // 128 threads x 4 partials each; keep dir halves separate
        float v0 = 0.f, v1 = 0.f;
        #pragma unroll
        for (int i = 0; i < 2; i++) {
            v0 += g_bpart[i * 128 + t];          // [0,256)  = dir0
            v1 += g_bpart[256 + i * 128 + t];    // [256,512)= dir1
        }
        #pragma unroll
        for (int o = 16; o > 0; o >>= 1) {
            v0 += __shfl_down_sync(0xffffffffu, v0, o);
            v1 += __shfl_down_sync(0xffffffffu, v1, o);
        }
        __shared__ float w0[4], w1[4];
        if ((t & 31) == 0) { w0[t >> 5] = v0; w1[t >> 5] = v1; }
        __syncthreads();
        if (t == 0) {
            const float inv = 1.f / (float)(BATCH * NPTS);
            float complete = (w0[0] + w0[1] + w0[2] + w0[3]) * inv;  // dir 0
            float accuracy = (w1[0] + w1[1] + w1[2] + w1[3]) * inv;  // dir 1
            out[0] = accuracy;
            out[1] = complete;
            out[2] = 0.5f * (accuracy + complete);
            g_count = 0;   // reset for next graph replay (deterministic)
        }
    }
}

extern "C" void kernel_launch(void* const* d_in, const int* in_sizes, int n_in,
                              void* d_out, int out_size) {
    const float* tar = (const float*)d_in[0];
    const float* src = (const float*)d_in[1];
    float* out = (float*)d_out;

    chamfer_kernel<<<dim3(QTILES * SPLITS, BATCH, 2), TPB>>>(tar, src);
    combine_kernel<<<CGRID, 128>>>(tar, src, out);
}